// round 12
// baseline (speedup 1.0000x reference)
#include <cuda_runtime.h>
#include <cuda_bf16.h>

#define NN 50000
#define EE 800000
#define D 96
#define ED 32
#define NB 391   // ceil(NN/128)

typedef unsigned long long ull;

#define PACK2(d, lo, hi)  asm("mov.b64 %0, {%1, %2};" : "=l"(d) : "f"(lo), "f"(hi))
#define UNPACK2(lo, hi, s) asm("mov.b64 {%0, %1}, %2;" : "=f"(lo), "=f"(hi) : "l"(s))
#define FMA2(d, a, b, c)  asm("fma.rn.f32x2 %0, %1, %2, %3;" : "=l"(d) : "l"(a), "l"(b), "l"(c))

// ---------------- static device scratch ----------------
__device__ __align__(16) int   g_deg[NN];
__device__ __align__(16) int   g_part[512];
__device__ __align__(16) int   g_rowptr[NN + 1];
__device__ __align__(16) int   g_fill[NN];
__device__ __align__(16) int   g_eidx[EE];   // CSR position -> edge id
__device__ __align__(16) int   g_src[EE];    // CSR position -> src node
__device__ __align__(16) float g_proj[(long long)EE * D];  // edge-ordered projections
__device__ __align__(16) float g_h [NN * D];
__device__ __align__(16) float g_h1[NN * D];
__device__ __align__(16) float g_h2[NN * D];
__device__ __align__(16) float g_sum[D];
__device__ __align__(16) float g_sumsq[D];
__device__ int g_is64;

__device__ __forceinline__ int load_idx(const void* ei, int pos) {
    if (g_is64) return (int)((const long long*)ei)[pos];
    return ((const int*)ei)[pos];
}
__device__ __forceinline__ int clampN(int v, int n) {
    return v < 0 ? 0 : (v >= n ? n - 1 : v);
}

// ---------------- init: dtype detect + zero ----------------
__global__ void k_init(const unsigned int* __restrict__ w) {
    int i = blockIdx.x * blockDim.x + threadIdx.x;
    if (blockIdx.x == 0 && threadIdx.x < 32) {
        unsigned v = w[2 * threadIdx.x + 1];
        unsigned b = __ballot_sync(0xffffffffu, v != 0u);
        if (threadIdx.x == 0) g_is64 = (b == 0u) ? 1 : 0;
    }
    if (i < NN) g_deg[i] = 0;
    if (i < D) { g_sum[i] = 0.f; g_sumsq[i] = 0.f; }
}

// ---------------- CSR build ----------------
__global__ void k_count(const void* __restrict__ ei) {
    int e = blockIdx.x * blockDim.x + threadIdx.x;
    if (e < EE) {
        int dst = load_idx(ei, EE + e);
        if ((unsigned)dst < (unsigned)NN) atomicAdd(&g_deg[dst], 1);
    }
}

__global__ void k_scan1() {
    __shared__ int s[128];
    int t = threadIdx.x;
    int i = blockIdx.x * 128 + t;
    s[t] = (i < NN) ? g_deg[i] : 0;
    __syncthreads();
    for (int off = 64; off; off >>= 1) {
        if (t < off) s[t] += s[t + off];
        __syncthreads();
    }
    if (t == 0) g_part[blockIdx.x] = s[0];
}

__global__ void k_scan2() {
    __shared__ int s[512];
    int t = threadIdx.x;
    s[t] = (t < NB) ? g_part[t] : 0;
    __syncthreads();
    for (int off = 1; off < 512; off <<= 1) {
        int u = (t >= off) ? s[t - off] : 0;
        __syncthreads();
        s[t] += u;
        __syncthreads();
    }
    if (t < NB) g_part[t] = s[t];
}

__global__ void k_scan3() {
    __shared__ int s[128];
    int t = threadIdx.x;
    int i = blockIdx.x * 128 + t;
    int v = (i < NN) ? g_deg[i] : 0;
    s[t] = v;
    __syncthreads();
    for (int off = 1; off < 128; off <<= 1) {
        int u = (t >= off) ? s[t - off] : 0;
        __syncthreads();
        s[t] += u;
        __syncthreads();
    }
    int base = blockIdx.x ? g_part[blockIdx.x - 1] : 0;
    if (i < NN) {
        int ex = base + s[t] - v;
        g_rowptr[i] = ex;
        g_fill[i]   = ex;
        if (i == NN - 1) g_rowptr[NN] = base + s[t];
    }
}

__global__ void k_fill(const void* __restrict__ ei) {
    int e = blockIdx.x * blockDim.x + threadIdx.x;
    if (e < EE) {
        int dst = load_idx(ei, EE + e);
        if ((unsigned)dst < (unsigned)NN) {
            int pos = atomicAdd(&g_fill[dst], 1);
            if ((unsigned)pos < (unsigned)EE) {
                g_eidx[pos] = e;
                g_src[pos]  = clampN(load_idx(ei, e), NN);
            }
        }
    }
}

// ---------------- Phase A: edge projection GEMM ----------------
// 256 threads / 64 edges per block; thread = (edge r, quarter h) computing 24 dims.
// acc = 12 ull (24 regs) -> target 4 blocks/SM (50% occ).
__global__ void __launch_bounds__(256, 4) k_edgemsg(
    const float* __restrict__ ea, const float* __restrict__ We,
    const float* __restrict__ be)
{
    __shared__ __align__(16) float We_s[ED * D];     // 12 KB
    __shared__ __align__(16) float ea_s[64 * 33];    // 8.4 KB
    __shared__ __align__(16) float t_buf[32 * 97];   // 12.4 KB transpose buffer
    __shared__ __align__(16) float be_s[D];

    int tid = threadIdx.x;
    long long e0 = (long long)blockIdx.x * 64;

    for (int i = tid; i < ED * D; i += 256) We_s[i] = We[i];
    if (tid < D) be_s[tid] = be[tid];
    for (int i = tid; i < 64 * ED; i += 256) {
        int r = i >> 5, c = i & 31;
        ea_s[r * 33 + c] = ea[(e0 + r) * ED + c];    // sequential stream, coalesced
    }
    __syncthreads();

    int r = tid >> 2, h = tid & 3;                   // edge row, dim quarter
    const float* wbase = We_s + h * 24;

    ull acc[12];
#pragma unroll
    for (int j = 0; j < 12; j++) PACK2(acc[j], be_s[h * 24 + 2 * j], be_s[h * 24 + 2 * j + 1]);

    const float* ea_row = ea_s + r * 33;
#pragma unroll 4
    for (int k = 0; k < ED; k++) {
        float hk = ea_row[k];
        ull hk2; PACK2(hk2, hk, hk);
        const ulonglong2* w2 = (const ulonglong2*)(wbase + k * D);
#pragma unroll
        for (int j = 0; j < 6; j++) {
            ulonglong2 w = w2[j];
            FMA2(acc[2 * j],     hk2, w.x, acc[2 * j]);
            FMA2(acc[2 * j + 1], hk2, w.y, acc[2 * j + 1]);
        }
    }

    // 2 halves of 32 edges: transpose through t_buf, coalesced global stores
    for (int q = 0; q < 2; q++) {
        __syncthreads();
        if ((r >> 5) == q) {
            int base = (r & 31) * 97 + h * 24;       // bank = (r + 24h + 2j) % 32: all distinct
#pragma unroll
            for (int j = 0; j < 12; j++) {
                float lo, hi;
                UNPACK2(lo, hi, acc[j]);
                t_buf[base + 2 * j]     = lo;
                t_buf[base + 2 * j + 1] = hi;
            }
        }
        __syncthreads();
        long long gbase = (e0 + (long long)q * 32) * D;
#pragma unroll
        for (int it = 0; it < 12; it++) {            // 32*96/256 = 12
            int f = it * 256 + tid;
            int row = f / D, col = f - row * D;
            g_proj[gbase + f] = t_buf[row * 97 + col];
        }
    }
}

// ---------------- Phase B: pull aggregation (warp per node) ----------------
__global__ void __launch_bounds__(256) k_aggr(const float* __restrict__ x)
{
    int warp = (blockIdx.x * blockDim.x + threadIdx.x) >> 5;
    int lane = threadIdx.x & 31;
    if (warp >= NN) return;

    int node = warp;
    int beg = g_rowptr[node], end = g_rowptr[node + 1];
    float a0 = 0.f, a1 = 0.f, a2 = 0.f;
    for (int p = beg; p < end; p++) {
        int e   = clampN(g_eidx[p], EE);
        int src = g_src[p];
        const float* pr = g_proj + (long long)e * D;
        const float* xs = x + (long long)src * D;
        a0 += fmaxf(xs[lane]      + pr[lane],      0.f);
        a1 += fmaxf(xs[lane + 32] + pr[lane + 32], 0.f);
        a2 += fmaxf(xs[lane + 64] + pr[lane + 64], 0.f);
    }
    const float* xn = x + (long long)node * D;
    g_h[node * D + lane]      = xn[lane]      + a0;
    g_h[node * D + lane + 32] = xn[lane + 32] + a1;
    g_h[node * D + lane + 64] = xn[lane + 64] + a2;
}

// ---------------- dense layer (FFMA2): stage 0: g_h->g_h1 (ReLU); stage 1: g_h1->g_h2 (+stats) ----------------
__global__ void __launch_bounds__(128) k_mlp(
    const float* __restrict__ W, const float* __restrict__ bias, int stage)
{
    __shared__ __align__(16) float Ws[32 * D];
    __shared__ __align__(16) float hs[128 * 33];

    const float* hin  = (stage == 0) ? g_h  : g_h1;
    float*       hout = (stage == 0) ? g_h1 : g_h2;

    int tid  = threadIdx.x;
    int base = blockIdx.x * 128;
    int node = base + tid;
    bool valid = node < NN;

    ull acc[48];
#pragma unroll
    for (int j = 0; j < 48; j++) { float c0 = bias[2 * j], c1 = bias[2 * j + 1]; PACK2(acc[j], c0, c1); }

    for (int kt = 0; kt < 3; kt++) {
        for (int i = tid; i < 32 * D; i += 128) Ws[i] = W[kt * 32 * D + i];
        for (int i = tid; i < 128 * 32; i += 128) {
            int r = i >> 5, kk = i & 31;
            int nd = base + r;
            hs[r * 33 + kk] = (nd < NN) ? hin[(long long)nd * D + kt * 32 + kk] : 0.f;
        }
        __syncthreads();

#pragma unroll 2
        for (int kk = 0; kk < 32; kk++) {
            float hk = hs[tid * 33 + kk];
            ull hk2; PACK2(hk2, hk, hk);
            const ulonglong2* w2 = (const ulonglong2*)(Ws + kk * D);
#pragma unroll
            for (int j = 0; j < 24; j++) {
                ulonglong2 w = w2[j];
                FMA2(acc[2 * j],     hk2, w.x, acc[2 * j]);
                FMA2(acc[2 * j + 1], hk2, w.y, acc[2 * j + 1]);
            }
        }
        __syncthreads();
    }

    float v[D];
#pragma unroll
    for (int j = 0; j < 48; j++) UNPACK2(v[2 * j], v[2 * j + 1], acc[j]);

    if (stage == 0) {
#pragma unroll
        for (int j = 0; j < D; j++) v[j] = fmaxf(v[j], 0.f);
    }
    if (valid) {
        float4* out4 = (float4*)(hout + (long long)node * D);
#pragma unroll
        for (int j4 = 0; j4 < D / 4; j4++)
            out4[j4] = make_float4(v[4 * j4], v[4 * j4 + 1], v[4 * j4 + 2], v[4 * j4 + 3]);
    }
    if (stage == 1) {
#pragma unroll
        for (int j = 0; j < D; j++) {
            float s1 = valid ? v[j] : 0.f;
            float s2 = s1 * s1;
            for (int off = 16; off; off >>= 1) {
                s1 += __shfl_down_sync(0xffffffffu, s1, off);
                s2 += __shfl_down_sync(0xffffffffu, s2, off);
            }
            if ((tid & 31) == 0) {
                atomicAdd(&g_sum[j],   s1);
                atomicAdd(&g_sumsq[j], s2);
            }
        }
    }
}

// ---------------- batchnorm + relu ----------------
__global__ void k_bn(const float* __restrict__ gamma,
                     const float* __restrict__ beta,
                     float* __restrict__ out)
{
    int i = blockIdx.x * blockDim.x + threadIdx.x;
    const int TOT4 = NN * D / 4;
    if (i >= TOT4) return;
    int c = (i * 4) % D;
    const float invN = 1.0f / (float)NN;
    float4 h = ((const float4*)g_h2)[i];
    float hv[4] = {h.x, h.y, h.z, h.w};
    float o[4];
#pragma unroll
    for (int u = 0; u < 4; u++) {
        int cc = c + u;
        float mean = g_sum[cc] * invN;
        float var  = g_sumsq[cc] * invN - mean * mean;
        float inv  = rsqrtf(var + 1e-5f);
        o[u] = fmaxf((hv[u] - mean) * inv * gamma[cc] + beta[cc], 0.f);
    }
    ((float4*)out)[i] = make_float4(o[0], o[1], o[2], o[3]);
}

// ---------------- launch (edgemsg at profiled slot 3) ----------------
extern "C" void kernel_launch(void* const* d_in, const int* in_sizes, int n_in,
                              void* d_out, int out_size)
{
    const float* x     = (const float*)d_in[0];
    const void*  ei    = d_in[1];
    const float* ea    = (const float*)d_in[2];
    const float* We    = (const float*)d_in[3];
    const float* be    = (const float*)d_in[4];
    const float* W1    = (const float*)d_in[5];
    const float* b1    = (const float*)d_in[6];
    const float* W2    = (const float*)d_in[7];
    const float* b2    = (const float*)d_in[8];
    const float* gamma = (const float*)d_in[9];
    const float* beta  = (const float*)d_in[10];
    float*       out   = (float*)d_out;

    k_init   <<<(NN + 255) / 256, 256>>>((const unsigned int*)ei);   // 0
    k_count  <<<(EE + 255) / 256, 256>>>(ei);                        // 1
    k_scan1  <<<NB, 128>>>();                                        // 2
    k_edgemsg<<<EE / 64, 256>>>(ea, We, be);                         // 3  <- profiled slot
    k_scan2  <<<1, 512>>>();                                         // 4
    k_scan3  <<<NB, 128>>>();                                        // 5
    k_fill   <<<(EE + 255) / 256, 256>>>(ei);                        // 6
    k_aggr   <<<NN / 8, 256>>>(x);                                   // 7
    k_mlp    <<<(NN + 127) / 128, 128>>>(W1, b1, 0);                 // 8
    k_mlp    <<<(NN + 127) / 128, 128>>>(W2, b2, 1);                 // 9
    k_bn     <<<(NN * D / 4 + 255) / 256, 256>>>(gamma, beta, out);  // 10
}

// round 13
// speedup vs baseline: 1.1425x; 1.1425x over previous
#include <cuda_runtime.h>
#include <cuda_bf16.h>

#define NN 50000
#define EE 800000
#define D 96
#define ED 32
#define NB 391   // ceil(NN/128)

typedef unsigned long long ull;

#define PACK2(d, lo, hi)  asm("mov.b64 %0, {%1, %2};" : "=l"(d) : "f"(lo), "f"(hi))
#define UNPACK2(lo, hi, s) asm("mov.b64 {%0, %1}, %2;" : "=f"(lo), "=f"(hi) : "l"(s))
#define FMA2(d, a, b, c)  asm("fma.rn.f32x2 %0, %1, %2, %3;" : "=l"(d) : "l"(a), "l"(b), "l"(c))

// ---------------- static device scratch ----------------
__device__ __align__(16) int   g_deg[NN];
__device__ __align__(16) int   g_part[512];
__device__ __align__(16) int   g_rowptr[NN + 1];
__device__ __align__(16) int   g_fill[NN];
__device__ __align__(16) int   g_eidx[EE];   // CSR position -> edge id
__device__ __align__(16) int   g_src[EE];    // CSR position -> src node
__device__ __align__(16) float g_proj[(long long)EE * D];  // edge-ordered projections
__device__ __align__(16) float g_h [NN * D];
__device__ __align__(16) float g_h1[NN * D];
__device__ __align__(16) float g_h2[NN * D];
__device__ __align__(16) float g_sum[D];
__device__ __align__(16) float g_sumsq[D];
__device__ int g_is64;

__device__ __forceinline__ int load_idx(const void* ei, int pos) {
    if (g_is64) return (int)((const long long*)ei)[pos];
    return ((const int*)ei)[pos];
}
__device__ __forceinline__ int clampN(int v, int n) {
    return v < 0 ? 0 : (v >= n ? n - 1 : v);
}

// ---------------- init: dtype detect + zero ----------------
__global__ void k_init(const unsigned int* __restrict__ w) {
    int i = blockIdx.x * blockDim.x + threadIdx.x;
    if (blockIdx.x == 0 && threadIdx.x < 32) {
        unsigned v = w[2 * threadIdx.x + 1];
        unsigned b = __ballot_sync(0xffffffffu, v != 0u);
        if (threadIdx.x == 0) g_is64 = (b == 0u) ? 1 : 0;
    }
    if (i < NN) g_deg[i] = 0;
    if (i < D) { g_sum[i] = 0.f; g_sumsq[i] = 0.f; }
}

// ---------------- CSR build ----------------
__global__ void k_count(const void* __restrict__ ei) {
    int e = blockIdx.x * blockDim.x + threadIdx.x;
    if (e < EE) {
        int dst = load_idx(ei, EE + e);
        if ((unsigned)dst < (unsigned)NN) atomicAdd(&g_deg[dst], 1);
    }
}

__global__ void k_scan1() {
    __shared__ int s[128];
    int t = threadIdx.x;
    int i = blockIdx.x * 128 + t;
    s[t] = (i < NN) ? g_deg[i] : 0;
    __syncthreads();
    for (int off = 64; off; off >>= 1) {
        if (t < off) s[t] += s[t + off];
        __syncthreads();
    }
    if (t == 0) g_part[blockIdx.x] = s[0];
}

__global__ void k_scan2() {
    __shared__ int s[512];
    int t = threadIdx.x;
    s[t] = (t < NB) ? g_part[t] : 0;
    __syncthreads();
    for (int off = 1; off < 512; off <<= 1) {
        int u = (t >= off) ? s[t - off] : 0;
        __syncthreads();
        s[t] += u;
        __syncthreads();
    }
    if (t < NB) g_part[t] = s[t];
}

__global__ void k_scan3() {
    __shared__ int s[128];
    int t = threadIdx.x;
    int i = blockIdx.x * 128 + t;
    int v = (i < NN) ? g_deg[i] : 0;
    s[t] = v;
    __syncthreads();
    for (int off = 1; off < 128; off <<= 1) {
        int u = (t >= off) ? s[t - off] : 0;
        __syncthreads();
        s[t] += u;
        __syncthreads();
    }
    int base = blockIdx.x ? g_part[blockIdx.x - 1] : 0;
    if (i < NN) {
        int ex = base + s[t] - v;
        g_rowptr[i] = ex;
        g_fill[i]   = ex;
        if (i == NN - 1) g_rowptr[NN] = base + s[t];
    }
}

__global__ void k_fill(const void* __restrict__ ei) {
    int e = blockIdx.x * blockDim.x + threadIdx.x;
    if (e < EE) {
        int dst = load_idx(ei, EE + e);
        if ((unsigned)dst < (unsigned)NN) {
            int pos = atomicAdd(&g_fill[dst], 1);
            if ((unsigned)pos < (unsigned)EE) {
                g_eidx[pos] = e;
                g_src[pos]  = clampN(load_idx(ei, e), NN);
            }
        }
    }
}

// ---------------- Phase A: edge projection GEMM ----------------
// 256 threads / 128 edges per block; thread = (quarter h, slot) handling
// 2 edges (slot, slot+64) x 24 dims. Each We LDS.128 feeds 2 edges:
// 8 LDS / 24 FMA2 per k per thread (3:1) vs 13:12 before.
__global__ void __launch_bounds__(256, 3) k_edgemsg(
    const float* __restrict__ ea, const float* __restrict__ We,
    const float* __restrict__ be)
{
    __shared__ __align__(16) float We_s[ED * D];     // 12 KB
    __shared__ __align__(16) float ea_s[128 * 33];   // 16.9 KB
    __shared__ __align__(16) float t_buf[32 * 97];   // 12.4 KB transpose buffer
    __shared__ __align__(16) float be_s[D];

    int tid = threadIdx.x;
    long long e0 = (long long)blockIdx.x * 128;

    for (int i = tid; i < ED * D; i += 256) We_s[i] = We[i];
    if (tid < D) be_s[tid] = be[tid];
    for (int i = tid; i < 128 * ED; i += 256) {
        int r = i >> 5, c = i & 31;
        ea_s[r * 33 + c] = ea[(e0 + r) * ED + c];    // sequential stream, coalesced
    }
    __syncthreads();

    int h    = tid & 3;                              // dim quarter (24 dims)
    int slot = tid >> 2;                             // 0..63: edges slot, slot+64
    const float* wbase = We_s + h * 24;

    ull accA[12], accB[12];
#pragma unroll
    for (int j = 0; j < 12; j++) {
        ull b; PACK2(b, be_s[h * 24 + 2 * j], be_s[h * 24 + 2 * j + 1]);
        accA[j] = b; accB[j] = b;
    }

    const float* rowA = ea_s + slot * 33;
    const float* rowB = ea_s + (slot + 64) * 33;
#pragma unroll 2
    for (int k = 0; k < ED; k++) {
        float ha = rowA[k], hb = rowB[k];
        ull ha2, hb2; PACK2(ha2, ha, ha); PACK2(hb2, hb, hb);
        const ulonglong2* w2 = (const ulonglong2*)(wbase + k * D);
#pragma unroll
        for (int j = 0; j < 6; j++) {
            ulonglong2 w = w2[j];
            FMA2(accA[2 * j],     ha2, w.x, accA[2 * j]);
            FMA2(accA[2 * j + 1], ha2, w.y, accA[2 * j + 1]);
            FMA2(accB[2 * j],     hb2, w.x, accB[2 * j]);
            FMA2(accB[2 * j + 1], hb2, w.y, accB[2 * j + 1]);
        }
    }

    // 4 quarters of 32 edges: q<2 from accA (edges 0-63), q>=2 from accB (64-127)
    for (int q = 0; q < 4; q++) {
        __syncthreads();
        ull* acc = (q < 2) ? accA : accB;
        int own = (q < 2) ? (slot >> 5) == q : (slot >> 5) == (q - 2);
        if (own) {
            int base = (slot & 31) * 97 + h * 24;    // bank = slot + 24h + 2j: all 32 distinct
#pragma unroll
            for (int j = 0; j < 12; j++) {
                float lo, hi;
                UNPACK2(lo, hi, acc[j]);
                t_buf[base + 2 * j]     = lo;
                t_buf[base + 2 * j + 1] = hi;
            }
        }
        __syncthreads();
        long long gbase = (e0 + (long long)q * 32) * D;
#pragma unroll
        for (int it = 0; it < 12; it++) {            // 32*96/256 = 12
            int f = it * 256 + tid;
            int row = f / D, col = f - row * D;
            g_proj[gbase + f] = t_buf[row * 97 + col];
        }
    }
}

// ---------------- Phase B: pull aggregation (warp per node) ----------------
__global__ void __launch_bounds__(256) k_aggr(const float* __restrict__ x)
{
    int warp = (blockIdx.x * blockDim.x + threadIdx.x) >> 5;
    int lane = threadIdx.x & 31;
    if (warp >= NN) return;

    int node = warp;
    int beg = g_rowptr[node], end = g_rowptr[node + 1];
    float a0 = 0.f, a1 = 0.f, a2 = 0.f;
    for (int p = beg; p < end; p++) {
        int e   = clampN(g_eidx[p], EE);
        int src = g_src[p];
        const float* pr = g_proj + (long long)e * D;
        const float* xs = x + (long long)src * D;
        a0 += fmaxf(xs[lane]      + pr[lane],      0.f);
        a1 += fmaxf(xs[lane + 32] + pr[lane + 32], 0.f);
        a2 += fmaxf(xs[lane + 64] + pr[lane + 64], 0.f);
    }
    const float* xn = x + (long long)node * D;
    g_h[node * D + lane]      = xn[lane]      + a0;
    g_h[node * D + lane + 32] = xn[lane + 32] + a1;
    g_h[node * D + lane + 64] = xn[lane + 64] + a2;
}

// ---------------- dense layer (FFMA2): stage 0: g_h->g_h1 (ReLU); stage 1: g_h1->g_h2 (+stats) ----------------
__global__ void __launch_bounds__(128) k_mlp(
    const float* __restrict__ W, const float* __restrict__ bias, int stage)
{
    __shared__ __align__(16) float Ws[32 * D];
    __shared__ __align__(16) float hs[128 * 33];

    const float* hin  = (stage == 0) ? g_h  : g_h1;
    float*       hout = (stage == 0) ? g_h1 : g_h2;

    int tid  = threadIdx.x;
    int base = blockIdx.x * 128;
    int node = base + tid;
    bool valid = node < NN;

    ull acc[48];
#pragma unroll
    for (int j = 0; j < 48; j++) { float c0 = bias[2 * j], c1 = bias[2 * j + 1]; PACK2(acc[j], c0, c1); }

    for (int kt = 0; kt < 3; kt++) {
        for (int i = tid; i < 32 * D; i += 128) Ws[i] = W[kt * 32 * D + i];
        for (int i = tid; i < 128 * 32; i += 128) {
            int r = i >> 5, kk = i & 31;
            int nd = base + r;
            hs[r * 33 + kk] = (nd < NN) ? hin[(long long)nd * D + kt * 32 + kk] : 0.f;
        }
        __syncthreads();

#pragma unroll 2
        for (int kk = 0; kk < 32; kk++) {
            float hk = hs[tid * 33 + kk];
            ull hk2; PACK2(hk2, hk, hk);
            const ulonglong2* w2 = (const ulonglong2*)(Ws + kk * D);
#pragma unroll
            for (int j = 0; j < 24; j++) {
                ulonglong2 w = w2[j];
                FMA2(acc[2 * j],     hk2, w.x, acc[2 * j]);
                FMA2(acc[2 * j + 1], hk2, w.y, acc[2 * j + 1]);
            }
        }
        __syncthreads();
    }

    float v[D];
#pragma unroll
    for (int j = 0; j < 48; j++) UNPACK2(v[2 * j], v[2 * j + 1], acc[j]);

    if (stage == 0) {
#pragma unroll
        for (int j = 0; j < D; j++) v[j] = fmaxf(v[j], 0.f);
    }
    if (valid) {
        float4* out4 = (float4*)(hout + (long long)node * D);
#pragma unroll
        for (int j4 = 0; j4 < D / 4; j4++)
            out4[j4] = make_float4(v[4 * j4], v[4 * j4 + 1], v[4 * j4 + 2], v[4 * j4 + 3]);
    }
    if (stage == 1) {
#pragma unroll
        for (int j = 0; j < D; j++) {
            float s1 = valid ? v[j] : 0.f;
            float s2 = s1 * s1;
            for (int off = 16; off; off >>= 1) {
                s1 += __shfl_down_sync(0xffffffffu, s1, off);
                s2 += __shfl_down_sync(0xffffffffu, s2, off);
            }
            if ((tid & 31) == 0) {
                atomicAdd(&g_sum[j],   s1);
                atomicAdd(&g_sumsq[j], s2);
            }
        }
    }
}

// ---------------- batchnorm + relu ----------------
__global__ void k_bn(const float* __restrict__ gamma,
                     const float* __restrict__ beta,
                     float* __restrict__ out)
{
    int i = blockIdx.x * blockDim.x + threadIdx.x;
    const int TOT4 = NN * D / 4;
    if (i >= TOT4) return;
    int c = (i * 4) % D;
    const float invN = 1.0f / (float)NN;
    float4 h = ((const float4*)g_h2)[i];
    float hv[4] = {h.x, h.y, h.z, h.w};
    float o[4];
#pragma unroll
    for (int u = 0; u < 4; u++) {
        int cc = c + u;
        float mean = g_sum[cc] * invN;
        float var  = g_sumsq[cc] * invN - mean * mean;
        float inv  = rsqrtf(var + 1e-5f);
        o[u] = fmaxf((hv[u] - mean) * inv * gamma[cc] + beta[cc], 0.f);
    }
    ((float4*)out)[i] = make_float4(o[0], o[1], o[2], o[3]);
}

// ---------------- launch (edgemsg at profiled slot 3) ----------------
extern "C" void kernel_launch(void* const* d_in, const int* in_sizes, int n_in,
                              void* d_out, int out_size)
{
    const float* x     = (const float*)d_in[0];
    const void*  ei    = d_in[1];
    const float* ea    = (const float*)d_in[2];
    const float* We    = (const float*)d_in[3];
    const float* be    = (const float*)d_in[4];
    const float* W1    = (const float*)d_in[5];
    const float* b1    = (const float*)d_in[6];
    const float* W2    = (const float*)d_in[7];
    const float* b2    = (const float*)d_in[8];
    const float* gamma = (const float*)d_in[9];
    const float* beta  = (const float*)d_in[10];
    float*       out   = (float*)d_out;

    k_init   <<<(NN + 255) / 256, 256>>>((const unsigned int*)ei);   // 0
    k_count  <<<(EE + 255) / 256, 256>>>(ei);                        // 1
    k_scan1  <<<NB, 128>>>();                                        // 2
    k_edgemsg<<<EE / 128, 256>>>(ea, We, be);                        // 3  <- profiled slot
    k_scan2  <<<1, 512>>>();                                         // 4
    k_scan3  <<<NB, 128>>>();                                        // 5
    k_fill   <<<(EE + 255) / 256, 256>>>(ei);                        // 6
    k_aggr   <<<NN / 8, 256>>>(x);                                   // 7
    k_mlp    <<<(NN + 127) / 128, 128>>>(W1, b1, 0);                 // 8
    k_mlp    <<<(NN + 127) / 128, 128>>>(W2, b2, 1);                 // 9
    k_bn     <<<(NN * D / 4 + 255) / 256, 256>>>(gamma, beta, out);  // 10
}

// round 15
// speedup vs baseline: 1.1783x; 1.0313x over previous
#include <cuda_runtime.h>
#include <cuda_bf16.h>

#define NN 50000
#define EE 800000
#define D 96
#define ED 32
#define NB 391   // ceil(NN/128)

typedef unsigned long long ull;
typedef long long ll;

#define PACK2(d, lo, hi)  asm("mov.b64 %0, {%1, %2};" : "=l"(d) : "f"(lo), "f"(hi))
#define UNPACK2(lo, hi, s) asm("mov.b64 {%0, %1}, %2;" : "=f"(lo), "=f"(hi) : "l"(s))
#define FMA2(d, a, b, c)  asm("fma.rn.f32x2 %0, %1, %2, %3;" : "=l"(d) : "l"(a), "l"(b), "l"(c))

// ---------------- static device scratch ----------------
__device__ __align__(16) int   g_deg[NN];
__device__ __align__(16) int   g_part[512];
__device__ __align__(16) int   g_rowptr[NN + 1];
__device__ __align__(16) int   g_fill[NN];
__device__ __align__(16) int   g_eidx[EE];   // CSR position -> edge id
__device__ __align__(16) int   g_src[EE];    // CSR position -> src node
__device__ __align__(16) float g_proj[(ll)EE * D];  // edge-ordered projections
__device__ __align__(16) float g_h [NN * D];
__device__ __align__(16) float g_h1[NN * D];
__device__ __align__(16) float g_h2[NN * D];
__device__ __align__(16) float g_sum[D];
__device__ __align__(16) float g_sumsq[D];
__device__ int g_is64;

__device__ __forceinline__ int load_idx(const void* ei, int pos) {
    if (g_is64) return (int)((const long long*)ei)[pos];
    return ((const int*)ei)[pos];
}
__device__ __forceinline__ int clampN(int v, int n) {
    return v < 0 ? 0 : (v >= n ? n - 1 : v);
}

// ---------------- init: dtype detect + zero ----------------
__global__ void k_init(const unsigned int* __restrict__ w) {
    int i = blockIdx.x * blockDim.x + threadIdx.x;
    if (blockIdx.x == 0 && threadIdx.x < 32) {
        unsigned v = w[2 * threadIdx.x + 1];
        unsigned b = __ballot_sync(0xffffffffu, v != 0u);
        if (threadIdx.x == 0) g_is64 = (b == 0u) ? 1 : 0;
    }
    if (i < NN) g_deg[i] = 0;
    if (i < D) { g_sum[i] = 0.f; g_sumsq[i] = 0.f; }
}

// ---------------- CSR build ----------------
__global__ void k_count(const void* __restrict__ ei) {
    int e = blockIdx.x * blockDim.x + threadIdx.x;
    if (e < EE) {
        int dst = load_idx(ei, EE + e);
        if ((unsigned)dst < (unsigned)NN) atomicAdd(&g_deg[dst], 1);
    }
}

__global__ void k_scan1() {
    __shared__ int s[128];
    int t = threadIdx.x;
    int i = blockIdx.x * 128 + t;
    s[t] = (i < NN) ? g_deg[i] : 0;
    __syncthreads();
    for (int off = 64; off; off >>= 1) {
        if (t < off) s[t] += s[t + off];
        __syncthreads();
    }
    if (t == 0) g_part[blockIdx.x] = s[0];
}

__global__ void k_scan2() {
    __shared__ int s[512];
    int t = threadIdx.x;
    s[t] = (t < NB) ? g_part[t] : 0;
    __syncthreads();
    for (int off = 1; off < 512; off <<= 1) {
        int u = (t >= off) ? s[t - off] : 0;
        __syncthreads();
        s[t] += u;
        __syncthreads();
    }
    if (t < NB) g_part[t] = s[t];
}

__global__ void k_scan3() {
    __shared__ int s[128];
    int t = threadIdx.x;
    int i = blockIdx.x * 128 + t;
    int v = (i < NN) ? g_deg[i] : 0;
    s[t] = v;
    __syncthreads();
    for (int off = 1; off < 128; off <<= 1) {
        int u = (t >= off) ? s[t - off] : 0;
        __syncthreads();
        s[t] += u;
        __syncthreads();
    }
    int base = blockIdx.x ? g_part[blockIdx.x - 1] : 0;
    if (i < NN) {
        int ex = base + s[t] - v;
        g_rowptr[i] = ex;
        g_fill[i]   = ex;
        if (i == NN - 1) g_rowptr[NN] = base + s[t];
    }
}

__global__ void k_fill(const void* __restrict__ ei) {
    int e = blockIdx.x * blockDim.x + threadIdx.x;
    if (e < EE) {
        int dst = load_idx(ei, EE + e);
        if ((unsigned)dst < (unsigned)NN) {
            int pos = atomicAdd(&g_fill[dst], 1);
            if ((unsigned)pos < (unsigned)EE) {
                g_eidx[pos] = e;
                g_src[pos]  = clampN(load_idx(ei, e), NN);
            }
        }
    }
}

// ---------------- Phase A: edge projection GEMM (R11-exact: half-split, 3 blocks/SM) ----------------
__global__ void __launch_bounds__(256, 3) k_edgemsg(
    const float* __restrict__ ea, const float* __restrict__ We,
    const float* __restrict__ be)
{
    __shared__ __align__(16) float We_s[ED * D];     // 12 KB
    __shared__ __align__(16) float ea_s[128 * 33];   // 16.9 KB
    __shared__ __align__(16) float t_buf[32 * 97];   // 12.4 KB transpose buffer
    __shared__ __align__(16) float be_s[D];

    int tid = threadIdx.x;
    ll e0 = (ll)blockIdx.x * 128;

    for (int i = tid; i < ED * D; i += 256) We_s[i] = We[i];
    if (tid < D) be_s[tid] = be[tid];
    for (int i = tid; i < 128 * ED; i += 256) {
        int r = i >> 5, c = i & 31;
        ea_s[r * 33 + c] = ea[(e0 + r) * ED + c];    // sequential stream, coalesced
    }
    __syncthreads();

    int r = tid >> 1, h = tid & 1;                   // edge row, dim half
    const float* wbase = We_s + h * 48;

    ull acc[24];
#pragma unroll
    for (int j = 0; j < 24; j++) PACK2(acc[j], be_s[h * 48 + 2 * j], be_s[h * 48 + 2 * j + 1]);

    const float* ea_row = ea_s + r * 33;
#pragma unroll 4
    for (int k = 0; k < ED; k++) {
        float hk = ea_row[k];
        ull hk2; PACK2(hk2, hk, hk);
        const ulonglong2* w2 = (const ulonglong2*)(wbase + k * D);
#pragma unroll
        for (int j = 0; j < 12; j++) {
            ulonglong2 w = w2[j];
            FMA2(acc[2 * j],     hk2, w.x, acc[2 * j]);
            FMA2(acc[2 * j + 1], hk2, w.y, acc[2 * j + 1]);
        }
    }

    // 4 quarters of 32 edges: transpose through t_buf, coalesced global stores
    for (int q = 0; q < 4; q++) {
        __syncthreads();
        if ((r >> 5) == q) {
            int base = (r & 31) * 97 + h * 48;       // conflict-free
#pragma unroll
            for (int j = 0; j < 24; j++) {
                float lo, hi;
                UNPACK2(lo, hi, acc[j]);
                t_buf[base + 2 * j]     = lo;
                t_buf[base + 2 * j + 1] = hi;
            }
        }
        __syncthreads();
        ll gbase = (e0 + (ll)q * 32) * D;
#pragma unroll
        for (int it = 0; it < 12; it++) {            // 32*96/256 = 12
            int f = it * 256 + tid;
            int row = f / D, col = f - row * D;
            g_proj[gbase + f] = t_buf[row * 97 + col];
        }
    }
}

// ---------------- Phase B: pull aggregation (warp per node, float4-wide, 2-edge unroll) ----------------
__global__ void __launch_bounds__(256) k_aggr(const float* __restrict__ x)
{
    int warp = (blockIdx.x * blockDim.x + threadIdx.x) >> 5;
    int lane = threadIdx.x & 31;
    if (warp >= NN) return;

    int beg = g_rowptr[warp], end = g_rowptr[warp + 1];
    bool act = lane < 24;                             // 24 lanes x float4 = 96 dims
    float4 acc = make_float4(0.f, 0.f, 0.f, 0.f);

    int p = beg;
    for (; p + 2 <= end; p += 2) {
        int e0 = clampN(g_eidx[p],     EE);
        int e1 = clampN(g_eidx[p + 1], EE);
        int s0 = g_src[p], s1 = g_src[p + 1];
        if (act) {
            float4 a0 = ((const float4*)(g_proj + (ll)e0 * D))[lane];
            float4 b0 = ((const float4*)(x      + (ll)s0 * D))[lane];
            float4 a1 = ((const float4*)(g_proj + (ll)e1 * D))[lane];
            float4 b1 = ((const float4*)(x      + (ll)s1 * D))[lane];
            acc.x += fmaxf(a0.x + b0.x, 0.f) + fmaxf(a1.x + b1.x, 0.f);
            acc.y += fmaxf(a0.y + b0.y, 0.f) + fmaxf(a1.y + b1.y, 0.f);
            acc.z += fmaxf(a0.z + b0.z, 0.f) + fmaxf(a1.z + b1.z, 0.f);
            acc.w += fmaxf(a0.w + b0.w, 0.f) + fmaxf(a1.w + b1.w, 0.f);
        }
    }
    if (p < end) {
        int e0 = clampN(g_eidx[p], EE);
        int s0 = g_src[p];
        if (act) {
            float4 a0 = ((const float4*)(g_proj + (ll)e0 * D))[lane];
            float4 b0 = ((const float4*)(x      + (ll)s0 * D))[lane];
            acc.x += fmaxf(a0.x + b0.x, 0.f);
            acc.y += fmaxf(a0.y + b0.y, 0.f);
            acc.z += fmaxf(a0.z + b0.z, 0.f);
            acc.w += fmaxf(a0.w + b0.w, 0.f);
        }
    }
    if (act) {
        float4 xv = ((const float4*)(x + (ll)warp * D))[lane];
        acc.x += xv.x; acc.y += xv.y; acc.z += xv.z; acc.w += xv.w;
        ((float4*)(g_h + (ll)warp * D))[lane] = acc;
    }
}

// ---------------- dense layer (FFMA2): stage 0: g_h->g_h1 (ReLU); stage 1: g_h1->g_h2 (+stats) ----------------
__global__ void __launch_bounds__(128) k_mlp(
    const float* __restrict__ W, const float* __restrict__ bias, int stage)
{
    __shared__ __align__(16) float Ws[32 * D];
    __shared__ __align__(16) float hs[128 * 33];

    const float* hin  = (stage == 0) ? g_h  : g_h1;
    float*       hout = (stage == 0) ? g_h1 : g_h2;

    int tid  = threadIdx.x;
    int base = blockIdx.x * 128;
    int node = base + tid;
    bool valid = node < NN;

    ull acc[48];
#pragma unroll
    for (int j = 0; j < 48; j++) { float c0 = bias[2 * j], c1 = bias[2 * j + 1]; PACK2(acc[j], c0, c1); }

    for (int kt = 0; kt < 3; kt++) {
        for (int i = tid; i < 32 * D; i += 128) Ws[i] = W[kt * 32 * D + i];
        for (int i = tid; i < 128 * 32; i += 128) {
            int r = i >> 5, kk = i & 31;
            int nd = base + r;
            hs[r * 33 + kk] = (nd < NN) ? hin[(ll)nd * D + kt * 32 + kk] : 0.f;
        }
        __syncthreads();

#pragma unroll 2
        for (int kk = 0; kk < 32; kk++) {
            float hk = hs[tid * 33 + kk];
            ull hk2; PACK2(hk2, hk, hk);
            const ulonglong2* w2 = (const ulonglong2*)(Ws + kk * D);
#pragma unroll
            for (int j = 0; j < 24; j++) {
                ulonglong2 w = w2[j];
                FMA2(acc[2 * j],     hk2, w.x, acc[2 * j]);
                FMA2(acc[2 * j + 1], hk2, w.y, acc[2 * j + 1]);
            }
        }
        __syncthreads();
    }

    float v[D];
#pragma unroll
    for (int j = 0; j < 48; j++) UNPACK2(v[2 * j], v[2 * j + 1], acc[j]);

    if (stage == 0) {
#pragma unroll
        for (int j = 0; j < D; j++) v[j] = fmaxf(v[j], 0.f);
    }
    if (valid) {
        float4* out4 = (float4*)(hout + (ll)node * D);
#pragma unroll
        for (int j4 = 0; j4 < D / 4; j4++)
            out4[j4] = make_float4(v[4 * j4], v[4 * j4 + 1], v[4 * j4 + 2], v[4 * j4 + 3]);
    }
    if (stage == 1) {
#pragma unroll
        for (int j = 0; j < D; j++) {
            float s1 = valid ? v[j] : 0.f;
            float s2 = s1 * s1;
            for (int off = 16; off; off >>= 1) {
                s1 += __shfl_down_sync(0xffffffffu, s1, off);
                s2 += __shfl_down_sync(0xffffffffu, s2, off);
            }
            if ((tid & 31) == 0) {
                atomicAdd(&g_sum[j],   s1);
                atomicAdd(&g_sumsq[j], s2);
            }
        }
    }
}

// ---------------- batchnorm + relu ----------------
__global__ void k_bn(const float* __restrict__ gamma,
                     const float* __restrict__ beta,
                     float* __restrict__ out)
{
    int i = blockIdx.x * blockDim.x + threadIdx.x;
    const int TOT4 = NN * D / 4;
    if (i >= TOT4) return;
    int c = (i * 4) % D;
    const float invN = 1.0f / (float)NN;
    float4 h = ((const float4*)g_h2)[i];
    float hv[4] = {h.x, h.y, h.z, h.w};
    float o[4];
#pragma unroll
    for (int u = 0; u < 4; u++) {
        int cc = c + u;
        float mean = g_sum[cc] * invN;
        float var  = g_sumsq[cc] * invN - mean * mean;
        float inv  = rsqrtf(var + 1e-5f);
        o[u] = fmaxf((hv[u] - mean) * inv * gamma[cc] + beta[cc], 0.f);
    }
    ((float4*)out)[i] = make_float4(o[0], o[1], o[2], o[3]);
}

// ---------------- launch (edgemsg at profiled slot 3) ----------------
extern "C" void kernel_launch(void* const* d_in, const int* in_sizes, int n_in,
                              void* d_out, int out_size)
{
    const float* x     = (const float*)d_in[0];
    const void*  ei    = d_in[1];
    const float* ea    = (const float*)d_in[2];
    const float* We    = (const float*)d_in[3];
    const float* be    = (const float*)d_in[4];
    const float* W1    = (const float*)d_in[5];
    const float* b1    = (const float*)d_in[6];
    const float* W2    = (const float*)d_in[7];
    const float* b2    = (const float*)d_in[8];
    const float* gamma = (const float*)d_in[9];
    const float* beta  = (const float*)d_in[10];
    float*       out   = (float*)d_out;

    k_init   <<<(NN + 255) / 256, 256>>>((const unsigned int*)ei);   // 0
    k_count  <<<(EE + 255) / 256, 256>>>(ei);                        // 1
    k_scan1  <<<NB, 128>>>();                                        // 2
    k_edgemsg<<<EE / 128, 256>>>(ea, We, be);                        // 3  <- profiled slot
    k_scan2  <<<1, 512>>>();                                         // 4
    k_scan3  <<<NB, 128>>>();                                        // 5
    k_fill   <<<(EE + 255) / 256, 256>>>(ei);                        // 6
    k_aggr   <<<NN / 8, 256>>>(x);                                   // 7
    k_mlp    <<<(NN + 127) / 128, 128>>>(W1, b1, 0);                 // 8
    k_mlp    <<<(NN + 127) / 128, 128>>>(W2, b2, 1);                 // 9
    k_bn     <<<(NN * D / 4 + 255) / 256, 256>>>(gamma, beta, out);  // 10
}

// round 16
// speedup vs baseline: 1.2861x; 1.0915x over previous
#include <cuda_runtime.h>
#include <cuda_bf16.h>

#define NN 50000
#define EE 800000
#define D 96
#define ED 32
#define NB 391   // ceil(NN/128)

typedef unsigned long long ull;
typedef long long ll;

#define PACK2(d, lo, hi)  asm("mov.b64 %0, {%1, %2};" : "=l"(d) : "f"(lo), "f"(hi))
#define UNPACK2(lo, hi, s) asm("mov.b64 {%0, %1}, %2;" : "=f"(lo), "=f"(hi) : "l"(s))
#define FMA2(d, a, b, c)  asm("fma.rn.f32x2 %0, %1, %2, %3;" : "=l"(d) : "l"(a), "l"(b), "l"(c))

// ---------------- static device scratch ----------------
__device__ __align__(16) int   g_deg[NN];
__device__ __align__(16) int   g_part[512];
__device__ __align__(16) int   g_rowptr[NN + 1];
__device__ __align__(16) int   g_fill[NN];
__device__ __align__(16) int   g_eidx[EE];   // CSR position -> edge id
__device__ __align__(16) int   g_src[EE];    // CSR position -> src node
__device__ __align__(16) float g_proj[(ll)EE * D];  // edge-ordered projections
__device__ __align__(16) float g_h [NN * D];
__device__ __align__(16) float g_h1[NN * D];
__device__ __align__(16) float g_h2[NN * D];
__device__ __align__(16) float g_sum[D];
__device__ __align__(16) float g_sumsq[D];
__device__ int g_is64;

__device__ __forceinline__ int load_idx(const void* ei, int pos) {
    if (g_is64) return (int)((const long long*)ei)[pos];
    return ((const int*)ei)[pos];
}
__device__ __forceinline__ int clampN(int v, int n) {
    return v < 0 ? 0 : (v >= n ? n - 1 : v);
}
__device__ __forceinline__ float to_tf32(float x) {
    unsigned u;
    asm("cvt.rna.tf32.f32 %0, %1;" : "=r"(u) : "f"(x));
    return __uint_as_float(u);
}

// ---------------- init: dtype detect + zero ----------------
__global__ void k_init(const unsigned int* __restrict__ w) {
    int i = blockIdx.x * blockDim.x + threadIdx.x;
    if (blockIdx.x == 0 && threadIdx.x < 32) {
        unsigned v = w[2 * threadIdx.x + 1];
        unsigned b = __ballot_sync(0xffffffffu, v != 0u);
        if (threadIdx.x == 0) g_is64 = (b == 0u) ? 1 : 0;
    }
    if (i < NN) g_deg[i] = 0;
    if (i < D) { g_sum[i] = 0.f; g_sumsq[i] = 0.f; }
}

// ---------------- CSR build ----------------
__global__ void k_count(const void* __restrict__ ei) {
    int e = blockIdx.x * blockDim.x + threadIdx.x;
    if (e < EE) {
        int dst = load_idx(ei, EE + e);
        if ((unsigned)dst < (unsigned)NN) atomicAdd(&g_deg[dst], 1);
    }
}

__global__ void k_scan1() {
    __shared__ int s[128];
    int t = threadIdx.x;
    int i = blockIdx.x * 128 + t;
    s[t] = (i < NN) ? g_deg[i] : 0;
    __syncthreads();
    for (int off = 64; off; off >>= 1) {
        if (t < off) s[t] += s[t + off];
        __syncthreads();
    }
    if (t == 0) g_part[blockIdx.x] = s[0];
}

__global__ void k_scan2() {
    __shared__ int s[512];
    int t = threadIdx.x;
    s[t] = (t < NB) ? g_part[t] : 0;
    __syncthreads();
    for (int off = 1; off < 512; off <<= 1) {
        int u = (t >= off) ? s[t - off] : 0;
        __syncthreads();
        s[t] += u;
        __syncthreads();
    }
    if (t < NB) g_part[t] = s[t];
}

__global__ void k_scan3() {
    __shared__ int s[128];
    int t = threadIdx.x;
    int i = blockIdx.x * 128 + t;
    int v = (i < NN) ? g_deg[i] : 0;
    s[t] = v;
    __syncthreads();
    for (int off = 1; off < 128; off <<= 1) {
        int u = (t >= off) ? s[t - off] : 0;
        __syncthreads();
        s[t] += u;
        __syncthreads();
    }
    int base = blockIdx.x ? g_part[blockIdx.x - 1] : 0;
    if (i < NN) {
        int ex = base + s[t] - v;
        g_rowptr[i] = ex;
        g_fill[i]   = ex;
        if (i == NN - 1) g_rowptr[NN] = base + s[t];
    }
}

__global__ void k_fill(const void* __restrict__ ei) {
    int e = blockIdx.x * blockDim.x + threadIdx.x;
    if (e < EE) {
        int dst = load_idx(ei, EE + e);
        if ((unsigned)dst < (unsigned)NN) {
            int pos = atomicAdd(&g_fill[dst], 1);
            if ((unsigned)pos < (unsigned)EE) {
                g_eidx[pos] = e;
                g_src[pos]  = clampN(load_idx(ei, e), NN);
            }
        }
    }
}

// ---------------- Phase A: edge projection GEMM via tf32 tensor cores ----------------
// 256 threads / 128 edges per block; warp w computes 16 edges x 96 dims with
// 48x mma.m16n8k8 (tf32). We pre-repacked to lane-indexed B-fragments (conflict-free
// LDS.64); ea converted to tf32 at smem fill; bias added in the transpose-out copy.
__global__ void __launch_bounds__(256, 3) k_edgemsg(
    const float* __restrict__ ea, const float* __restrict__ We,
    const float* __restrict__ be)
{
    __shared__ __align__(16) float  ea_s[128 * 33];     // 16.9 KB (tf32 values)
    __shared__ __align__(16) float2 Bfrag_s[4 * 12 * 32]; // 12 KB
    __shared__ __align__(16) float  t_buf[32 * 98];     // 12.5 KB (even pad for STS.64)
    __shared__ __align__(16) float  be_s[D];

    int tid = threadIdx.x;
    ll e0 = (ll)blockIdx.x * 128;

    // repack We -> B fragments: Bfrag[kk][n][lane] = (We[kk*8+q][n*8+g], We[kk*8+q+4][n*8+g])
    for (int i = tid; i < 1536; i += 256) {
        int kk = i / 384, rem = i - kk * 384;
        int n = rem >> 5, lane = rem & 31;
        int q = lane & 3, g = lane >> 2;
        int col = n * 8 + g;
        float b0 = to_tf32(We[(kk * 8 + q) * D + col]);
        float b1 = to_tf32(We[(kk * 8 + q + 4) * D + col]);
        Bfrag_s[i] = make_float2(b0, b1);
    }
    if (tid < D) be_s[tid] = be[tid];
    for (int i = tid; i < 128 * ED; i += 256) {
        int r = i >> 5, c = i & 31;
        ea_s[r * 33 + c] = to_tf32(ea[(e0 + r) * ED + c]);  // coalesced stream
    }
    __syncthreads();

    int warp = tid >> 5, lane = tid & 31;
    int g = lane >> 2, q = lane & 3;

    float d[48];
#pragma unroll
    for (int j = 0; j < 48; j++) d[j] = 0.f;

    const float* arow0 = ea_s + (warp * 16 + g) * 33;
    const float* arow1 = arow0 + 8 * 33;
#pragma unroll
    for (int kk = 0; kk < 4; kk++) {
        unsigned a0 = __float_as_uint(arow0[kk * 8 + q]);
        unsigned a1 = __float_as_uint(arow1[kk * 8 + q]);
        unsigned a2 = __float_as_uint(arow0[kk * 8 + q + 4]);
        unsigned a3 = __float_as_uint(arow1[kk * 8 + q + 4]);
        const float2* bp = Bfrag_s + kk * 12 * 32 + lane;
#pragma unroll
        for (int n = 0; n < 12; n++) {
            float2 b = bp[n * 32];
            asm volatile(
                "mma.sync.aligned.m16n8k8.row.col.f32.tf32.tf32.f32 "
                "{%0,%1,%2,%3}, {%4,%5,%6,%7}, {%8,%9}, {%0,%1,%2,%3};"
                : "+f"(d[n * 4]), "+f"(d[n * 4 + 1]), "+f"(d[n * 4 + 2]), "+f"(d[n * 4 + 3])
                : "r"(a0), "r"(a1), "r"(a2), "r"(a3),
                  "r"(__float_as_uint(b.x)), "r"(__float_as_uint(b.y)));
        }
    }

    // 4 rounds of 32 edges: warps 2qq,2qq+1 dump D frags, then coalesced store + bias
    for (int qq = 0; qq < 4; qq++) {
        __syncthreads();
        if ((warp >> 1) == qq) {
            float* tb = t_buf + ((warp & 1) * 16 + g) * 98;
#pragma unroll
            for (int n = 0; n < 12; n++) {
                int col = n * 8 + 2 * q;
                *(float2*)(tb + col)          = make_float2(d[n * 4],     d[n * 4 + 1]);
                *(float2*)(tb + 8 * 98 + col) = make_float2(d[n * 4 + 2], d[n * 4 + 3]);
            }
        }
        __syncthreads();
        ll gbase = (e0 + (ll)qq * 32) * D;
#pragma unroll
        for (int it = 0; it < 12; it++) {            // 32*96/256 = 12
            int f = it * 256 + tid;
            int row = f / D, col = f - row * D;
            g_proj[gbase + f] = t_buf[row * 98 + col] + be_s[col];
        }
    }
}

// ---------------- Phase B: pull aggregation (warp per node, float4-wide, 2-edge unroll) ----------------
__global__ void __launch_bounds__(256) k_aggr(const float* __restrict__ x)
{
    int warp = (blockIdx.x * blockDim.x + threadIdx.x) >> 5;
    int lane = threadIdx.x & 31;
    if (warp >= NN) return;

    int beg = g_rowptr[warp], end = g_rowptr[warp + 1];
    bool act = lane < 24;                             // 24 lanes x float4 = 96 dims
    float4 acc = make_float4(0.f, 0.f, 0.f, 0.f);

    int p = beg;
    for (; p + 2 <= end; p += 2) {
        int e0 = clampN(g_eidx[p],     EE);
        int e1 = clampN(g_eidx[p + 1], EE);
        int s0 = g_src[p], s1 = g_src[p + 1];
        if (act) {
            float4 a0 = ((const float4*)(g_proj + (ll)e0 * D))[lane];
            float4 b0 = ((const float4*)(x      + (ll)s0 * D))[lane];
            float4 a1 = ((const float4*)(g_proj + (ll)e1 * D))[lane];
            float4 b1 = ((const float4*)(x      + (ll)s1 * D))[lane];
            acc.x += fmaxf(a0.x + b0.x, 0.f) + fmaxf(a1.x + b1.x, 0.f);
            acc.y += fmaxf(a0.y + b0.y, 0.f) + fmaxf(a1.y + b1.y, 0.f);
            acc.z += fmaxf(a0.z + b0.z, 0.f) + fmaxf(a1.z + b1.z, 0.f);
            acc.w += fmaxf(a0.w + b0.w, 0.f) + fmaxf(a1.w + b1.w, 0.f);
        }
    }
    if (p < end) {
        int e0 = clampN(g_eidx[p], EE);
        int s0 = g_src[p];
        if (act) {
            float4 a0 = ((const float4*)(g_proj + (ll)e0 * D))[lane];
            float4 b0 = ((const float4*)(x      + (ll)s0 * D))[lane];
            acc.x += fmaxf(a0.x + b0.x, 0.f);
            acc.y += fmaxf(a0.y + b0.y, 0.f);
            acc.z += fmaxf(a0.z + b0.z, 0.f);
            acc.w += fmaxf(a0.w + b0.w, 0.f);
        }
    }
    if (act) {
        float4 xv = ((const float4*)(x + (ll)warp * D))[lane];
        acc.x += xv.x; acc.y += xv.y; acc.z += xv.z; acc.w += xv.w;
        ((float4*)(g_h + (ll)warp * D))[lane] = acc;
    }
}

// ---------------- dense layer (FFMA2): stage 0: g_h->g_h1 (ReLU); stage 1: g_h1->g_h2 (+stats) ----------------
__global__ void __launch_bounds__(128) k_mlp(
    const float* __restrict__ W, const float* __restrict__ bias, int stage)
{
    __shared__ __align__(16) float Ws[32 * D];
    __shared__ __align__(16) float hs[128 * 33];

    const float* hin  = (stage == 0) ? g_h  : g_h1;
    float*       hout = (stage == 0) ? g_h1 : g_h2;

    int tid  = threadIdx.x;
    int base = blockIdx.x * 128;
    int node = base + tid;
    bool valid = node < NN;

    ull acc[48];
#pragma unroll
    for (int j = 0; j < 48; j++) { float c0 = bias[2 * j], c1 = bias[2 * j + 1]; PACK2(acc[j], c0, c1); }

    for (int kt = 0; kt < 3; kt++) {
        for (int i = tid; i < 32 * D; i += 128) Ws[i] = W[kt * 32 * D + i];
        for (int i = tid; i < 128 * 32; i += 128) {
            int r = i >> 5, kk = i & 31;
            int nd = base + r;
            hs[r * 33 + kk] = (nd < NN) ? hin[(ll)nd * D + kt * 32 + kk] : 0.f;
        }
        __syncthreads();

#pragma unroll 2
        for (int kk = 0; kk < 32; kk++) {
            float hk = hs[tid * 33 + kk];
            ull hk2; PACK2(hk2, hk, hk);
            const ulonglong2* w2 = (const ulonglong2*)(Ws + kk * D);
#pragma unroll
            for (int j = 0; j < 24; j++) {
                ulonglong2 w = w2[j];
                FMA2(acc[2 * j],     hk2, w.x, acc[2 * j]);
                FMA2(acc[2 * j + 1], hk2, w.y, acc[2 * j + 1]);
            }
        }
        __syncthreads();
    }

    float v[D];
#pragma unroll
    for (int j = 0; j < 48; j++) UNPACK2(v[2 * j], v[2 * j + 1], acc[j]);

    if (stage == 0) {
#pragma unroll
        for (int j = 0; j < D; j++) v[j] = fmaxf(v[j], 0.f);
    }
    if (valid) {
        float4* out4 = (float4*)(hout + (ll)node * D);
#pragma unroll
        for (int j4 = 0; j4 < D / 4; j4++)
            out4[j4] = make_float4(v[4 * j4], v[4 * j4 + 1], v[4 * j4 + 2], v[4 * j4 + 3]);
    }
    if (stage == 1) {
#pragma unroll
        for (int j = 0; j < D; j++) {
            float s1 = valid ? v[j] : 0.f;
            float s2 = s1 * s1;
            for (int off = 16; off; off >>= 1) {
                s1 += __shfl_down_sync(0xffffffffu, s1, off);
                s2 += __shfl_down_sync(0xffffffffu, s2, off);
            }
            if ((tid & 31) == 0) {
                atomicAdd(&g_sum[j],   s1);
                atomicAdd(&g_sumsq[j], s2);
            }
        }
    }
}

// ---------------- batchnorm + relu ----------------
__global__ void k_bn(const float* __restrict__ gamma,
                     const float* __restrict__ beta,
                     float* __restrict__ out)
{
    int i = blockIdx.x * blockDim.x + threadIdx.x;
    const int TOT4 = NN * D / 4;
    if (i >= TOT4) return;
    int c = (i * 4) % D;
    const float invN = 1.0f / (float)NN;
    float4 h = ((const float4*)g_h2)[i];
    float hv[4] = {h.x, h.y, h.z, h.w};
    float o[4];
#pragma unroll
    for (int u = 0; u < 4; u++) {
        int cc = c + u;
        float mean = g_sum[cc] * invN;
        float var  = g_sumsq[cc] * invN - mean * mean;
        float inv  = rsqrtf(var + 1e-5f);
        o[u] = fmaxf((hv[u] - mean) * inv * gamma[cc] + beta[cc], 0.f);
    }
    ((float4*)out)[i] = make_float4(o[0], o[1], o[2], o[3]);
}

// ---------------- launch (edgemsg at profiled slot 3) ----------------
extern "C" void kernel_launch(void* const* d_in, const int* in_sizes, int n_in,
                              void* d_out, int out_size)
{
    const float* x     = (const float*)d_in[0];
    const void*  ei    = d_in[1];
    const float* ea    = (const float*)d_in[2];
    const float* We    = (const float*)d_in[3];
    const float* be    = (const float*)d_in[4];
    const float* W1    = (const float*)d_in[5];
    const float* b1    = (const float*)d_in[6];
    const float* W2    = (const float*)d_in[7];
    const float* b2    = (const float*)d_in[8];
    const float* gamma = (const float*)d_in[9];
    const float* beta  = (const float*)d_in[10];
    float*       out   = (float*)d_out;

    k_init   <<<(NN + 255) / 256, 256>>>((const unsigned int*)ei);   // 0
    k_count  <<<(EE + 255) / 256, 256>>>(ei);                        // 1
    k_scan1  <<<NB, 128>>>();                                        // 2
    k_edgemsg<<<EE / 128, 256>>>(ea, We, be);                        // 3  <- profiled slot
    k_scan2  <<<1, 512>>>();                                         // 4
    k_scan3  <<<NB, 128>>>();                                        // 5
    k_fill   <<<(EE + 255) / 256, 256>>>(ei);                        // 6
    k_aggr   <<<NN / 8, 256>>>(x);                                   // 7
    k_mlp    <<<(NN + 127) / 128, 128>>>(W1, b1, 0);                 // 8
    k_mlp    <<<(NN + 127) / 128, 128>>>(W2, b2, 1);                 // 9
    k_bn     <<<(NN * D / 4 + 255) / 256, 256>>>(gamma, beta, out);  // 10
}

// round 17
// speedup vs baseline: 1.7586x; 1.3673x over previous
#include <cuda_runtime.h>
#include <cuda_bf16.h>

#define NN 50000
#define EE 800000
#define D 96
#define ED 32
#define NB 391   // ceil(NN/128)

typedef unsigned long long ull;
typedef long long ll;

// ---------------- static device scratch ----------------
__device__ __align__(16) int    g_deg[NN];
__device__ __align__(16) int    g_part[512];
__device__ __align__(16) int    g_rowptr[NN + 1];
__device__ __align__(16) int    g_fill[NN];
__device__ __align__(16) int    g_eidx[EE];   // CSR position -> edge id
__device__ __align__(16) int    g_src[EE];    // CSR position -> src node
__device__ __align__(16) float  g_proj[(ll)EE * D];  // edge-ordered projections
__device__ __align__(16) float  g_h [NN * D];
__device__ __align__(16) float  g_h1[NN * D];
__device__ __align__(16) float  g_h2[NN * D];
__device__ __align__(16) float  g_sum[D];
__device__ __align__(16) float  g_sumsq[D];
__device__ __align__(16) float2 g_wfrag[2 * 4608];   // tf32 B-fragments for W1/W2
__device__ int g_is64;

__device__ __forceinline__ int load_idx(const void* ei, int pos) {
    if (g_is64) return (int)((const long long*)ei)[pos];
    return ((const int*)ei)[pos];
}
__device__ __forceinline__ int clampN(int v, int n) {
    return v < 0 ? 0 : (v >= n ? n - 1 : v);
}
__device__ __forceinline__ float to_tf32(float x) {
    unsigned u;
    asm("cvt.rna.tf32.f32 %0, %1;" : "=r"(u) : "f"(x));
    return __uint_as_float(u);
}

// ---------------- init: dtype detect + zero ----------------
__global__ void k_init(const unsigned int* __restrict__ w) {
    int i = blockIdx.x * blockDim.x + threadIdx.x;
    if (blockIdx.x == 0 && threadIdx.x < 32) {
        unsigned v = w[2 * threadIdx.x + 1];
        unsigned b = __ballot_sync(0xffffffffu, v != 0u);
        if (threadIdx.x == 0) g_is64 = (b == 0u) ? 1 : 0;
    }
    if (i < NN) g_deg[i] = 0;
    if (i < D) { g_sum[i] = 0.f; g_sumsq[i] = 0.f; }
}

// ---------------- weight fragment prep (W1,W2 -> tf32 MMA B-fragments) ----------------
__global__ void k_prep(const float* __restrict__ W1, const float* __restrict__ W2) {
    int i = blockIdx.x * blockDim.x + threadIdx.x;
    if (i >= 2 * 4608) return;
    int layer = i / 4608, rem = i - layer * 4608;
    int kk = rem / 384, r2 = rem - kk * 384;
    int n = r2 >> 5, lane = r2 & 31;
    int q = lane & 3, g = lane >> 2;
    const float* W = layer ? W2 : W1;
    int col = n * 8 + g;
    g_wfrag[i] = make_float2(to_tf32(W[(kk * 8 + q) * D + col]),
                             to_tf32(W[(kk * 8 + q + 4) * D + col]));
}

// ---------------- CSR build ----------------
__global__ void k_count(const void* __restrict__ ei) {
    int e = blockIdx.x * blockDim.x + threadIdx.x;
    if (e < EE) {
        int dst = load_idx(ei, EE + e);
        if ((unsigned)dst < (unsigned)NN) atomicAdd(&g_deg[dst], 1);
    }
}

__global__ void k_scan1() {
    __shared__ int s[128];
    int t = threadIdx.x;
    int i = blockIdx.x * 128 + t;
    s[t] = (i < NN) ? g_deg[i] : 0;
    __syncthreads();
    for (int off = 64; off; off >>= 1) {
        if (t < off) s[t] += s[t + off];
        __syncthreads();
    }
    if (t == 0) g_part[blockIdx.x] = s[0];
}

__global__ void k_scan2() {
    __shared__ int s[512];
    int t = threadIdx.x;
    s[t] = (t < NB) ? g_part[t] : 0;
    __syncthreads();
    for (int off = 1; off < 512; off <<= 1) {
        int u = (t >= off) ? s[t - off] : 0;
        __syncthreads();
        s[t] += u;
        __syncthreads();
    }
    if (t < NB) g_part[t] = s[t];
}

__global__ void k_scan3() {
    __shared__ int s[128];
    int t = threadIdx.x;
    int i = blockIdx.x * 128 + t;
    int v = (i < NN) ? g_deg[i] : 0;
    s[t] = v;
    __syncthreads();
    for (int off = 1; off < 128; off <<= 1) {
        int u = (t >= off) ? s[t - off] : 0;
        __syncthreads();
        s[t] += u;
        __syncthreads();
    }
    int base = blockIdx.x ? g_part[blockIdx.x - 1] : 0;
    if (i < NN) {
        int ex = base + s[t] - v;
        g_rowptr[i] = ex;
        g_fill[i]   = ex;
        if (i == NN - 1) g_rowptr[NN] = base + s[t];
    }
}

__global__ void k_fill(const void* __restrict__ ei) {
    int e = blockIdx.x * blockDim.x + threadIdx.x;
    if (e < EE) {
        int dst = load_idx(ei, EE + e);
        if ((unsigned)dst < (unsigned)NN) {
            int pos = atomicAdd(&g_fill[dst], 1);
            if ((unsigned)pos < (unsigned)EE) {
                g_eidx[pos] = e;
                g_src[pos]  = clampN(load_idx(ei, e), NN);
            }
        }
    }
}

// ---------------- Phase A: edge projection GEMM via tf32 tensor cores (R16-exact) ----------------
__global__ void __launch_bounds__(256, 3) k_edgemsg(
    const float* __restrict__ ea, const float* __restrict__ We,
    const float* __restrict__ be)
{
    __shared__ __align__(16) float  ea_s[128 * 33];       // 16.9 KB (tf32 values)
    __shared__ __align__(16) float2 Bfrag_s[4 * 12 * 32]; // 12 KB
    __shared__ __align__(16) float  t_buf[32 * 98];       // 12.5 KB
    __shared__ __align__(16) float  be_s[D];

    int tid = threadIdx.x;
    ll e0 = (ll)blockIdx.x * 128;

    for (int i = tid; i < 1536; i += 256) {
        int kk = i / 384, rem = i - kk * 384;
        int n = rem >> 5, lane = rem & 31;
        int q = lane & 3, g = lane >> 2;
        int col = n * 8 + g;
        float b0 = to_tf32(We[(kk * 8 + q) * D + col]);
        float b1 = to_tf32(We[(kk * 8 + q + 4) * D + col]);
        Bfrag_s[i] = make_float2(b0, b1);
    }
    if (tid < D) be_s[tid] = be[tid];
    for (int i = tid; i < 128 * ED; i += 256) {
        int r = i >> 5, c = i & 31;
        ea_s[r * 33 + c] = to_tf32(ea[(e0 + r) * ED + c]);
    }
    __syncthreads();

    int warp = tid >> 5, lane = tid & 31;
    int g = lane >> 2, q = lane & 3;

    float d[48];
#pragma unroll
    for (int j = 0; j < 48; j++) d[j] = 0.f;

    const float* arow0 = ea_s + (warp * 16 + g) * 33;
    const float* arow1 = arow0 + 8 * 33;
#pragma unroll
    for (int kk = 0; kk < 4; kk++) {
        unsigned a0 = __float_as_uint(arow0[kk * 8 + q]);
        unsigned a1 = __float_as_uint(arow1[kk * 8 + q]);
        unsigned a2 = __float_as_uint(arow0[kk * 8 + q + 4]);
        unsigned a3 = __float_as_uint(arow1[kk * 8 + q + 4]);
        const float2* bp = Bfrag_s + kk * 12 * 32 + lane;
#pragma unroll
        for (int n = 0; n < 12; n++) {
            float2 b = bp[n * 32];
            asm volatile(
                "mma.sync.aligned.m16n8k8.row.col.f32.tf32.tf32.f32 "
                "{%0,%1,%2,%3}, {%4,%5,%6,%7}, {%8,%9}, {%0,%1,%2,%3};"
                : "+f"(d[n * 4]), "+f"(d[n * 4 + 1]), "+f"(d[n * 4 + 2]), "+f"(d[n * 4 + 3])
                : "r"(a0), "r"(a1), "r"(a2), "r"(a3),
                  "r"(__float_as_uint(b.x)), "r"(__float_as_uint(b.y)));
        }
    }

    for (int qq = 0; qq < 4; qq++) {
        __syncthreads();
        if ((warp >> 1) == qq) {
            float* tb = t_buf + ((warp & 1) * 16 + g) * 98;
#pragma unroll
            for (int n = 0; n < 12; n++) {
                int col = n * 8 + 2 * q;
                *(float2*)(tb + col)          = make_float2(d[n * 4],     d[n * 4 + 1]);
                *(float2*)(tb + 8 * 98 + col) = make_float2(d[n * 4 + 2], d[n * 4 + 3]);
            }
        }
        __syncthreads();
        ll gbase = (e0 + (ll)qq * 32) * D;
#pragma unroll
        for (int it = 0; it < 12; it++) {
            int f = it * 256 + tid;
            int row = f / D, col = f - row * D;
            g_proj[gbase + f] = t_buf[row * 98 + col] + be_s[col];
        }
    }
}

// ---------------- Phase B: pull aggregation (warp per node, float4-wide, 4-edge unroll) ----------------
__global__ void __launch_bounds__(256) k_aggr(const float* __restrict__ x)
{
    int warp = (blockIdx.x * blockDim.x + threadIdx.x) >> 5;
    int lane = threadIdx.x & 31;
    if (warp >= NN) return;

    int beg = g_rowptr[warp], end = g_rowptr[warp + 1];
    bool act = lane < 24;
    float4 acc = make_float4(0.f, 0.f, 0.f, 0.f);

    int p = beg;
    for (; p + 4 <= end; p += 4) {
        int e0 = clampN(g_eidx[p],     EE), e1 = clampN(g_eidx[p + 1], EE);
        int e2 = clampN(g_eidx[p + 2], EE), e3 = clampN(g_eidx[p + 3], EE);
        int s0 = g_src[p], s1 = g_src[p + 1], s2 = g_src[p + 2], s3 = g_src[p + 3];
        if (act) {
            float4 a0 = ((const float4*)(g_proj + (ll)e0 * D))[lane];
            float4 a1 = ((const float4*)(g_proj + (ll)e1 * D))[lane];
            float4 a2 = ((const float4*)(g_proj + (ll)e2 * D))[lane];
            float4 a3 = ((const float4*)(g_proj + (ll)e3 * D))[lane];
            float4 b0 = ((const float4*)(x + (ll)s0 * D))[lane];
            float4 b1 = ((const float4*)(x + (ll)s1 * D))[lane];
            float4 b2 = ((const float4*)(x + (ll)s2 * D))[lane];
            float4 b3 = ((const float4*)(x + (ll)s3 * D))[lane];
            acc.x += fmaxf(a0.x + b0.x, 0.f) + fmaxf(a1.x + b1.x, 0.f)
                   + fmaxf(a2.x + b2.x, 0.f) + fmaxf(a3.x + b3.x, 0.f);
            acc.y += fmaxf(a0.y + b0.y, 0.f) + fmaxf(a1.y + b1.y, 0.f)
                   + fmaxf(a2.y + b2.y, 0.f) + fmaxf(a3.y + b3.y, 0.f);
            acc.z += fmaxf(a0.z + b0.z, 0.f) + fmaxf(a1.z + b1.z, 0.f)
                   + fmaxf(a2.z + b2.z, 0.f) + fmaxf(a3.z + b3.z, 0.f);
            acc.w += fmaxf(a0.w + b0.w, 0.f) + fmaxf(a1.w + b1.w, 0.f)
                   + fmaxf(a2.w + b2.w, 0.f) + fmaxf(a3.w + b3.w, 0.f);
        }
    }
    for (; p < end; p++) {
        int e0 = clampN(g_eidx[p], EE);
        int s0 = g_src[p];
        if (act) {
            float4 a0 = ((const float4*)(g_proj + (ll)e0 * D))[lane];
            float4 b0 = ((const float4*)(x + (ll)s0 * D))[lane];
            acc.x += fmaxf(a0.x + b0.x, 0.f);
            acc.y += fmaxf(a0.y + b0.y, 0.f);
            acc.z += fmaxf(a0.z + b0.z, 0.f);
            acc.w += fmaxf(a0.w + b0.w, 0.f);
        }
    }
    if (act) {
        float4 xv = ((const float4*)(x + (ll)warp * D))[lane];
        acc.x += xv.x; acc.y += xv.y; acc.z += xv.z; acc.w += xv.w;
        ((float4*)(g_h + (ll)warp * D))[lane] = acc;
    }
}

// ---------------- dense layer via tf32 MMA: 64 nodes / 128 threads per block ----------------
// stage 0: g_h -> g_h1 (ReLU); stage 1: g_h1 -> g_h2 (+BN stats)
__global__ void __launch_bounds__(128) k_mlp(const float* __restrict__ bias, int stage)
{
    __shared__ __align__(16) float hs[64 * 98];      // 25.1 KB: A tile, then D tile

    const float* hin  = (stage == 0) ? g_h  : g_h1;
    float*       hout = (stage == 0) ? g_h1 : g_h2;

    int tid = threadIdx.x;
    int node0 = blockIdx.x * 64;
    int nvalid = NN - node0; if (nvalid > 64) nvalid = 64;

    for (int f = tid; f < 64 * D; f += 128) {
        int r = f / D, c = f - r * D;
        float v = (r < nvalid) ? hin[(ll)(node0 + r) * D + c] : 0.f;
        hs[r * 98 + c] = to_tf32(v);
    }
    __syncthreads();

    int warp = tid >> 5, lane = tid & 31;
    int g = lane >> 2, q = lane & 3;

    float d[48];
#pragma unroll
    for (int j = 0; j < 48; j++) d[j] = 0.f;

    const float*  arow0 = hs + (warp * 16 + g) * 98;
    const float*  arow1 = arow0 + 8 * 98;
    const float2* wf    = g_wfrag + stage * 4608 + lane;
#pragma unroll
    for (int kk = 0; kk < 12; kk++) {
        unsigned a0 = __float_as_uint(arow0[kk * 8 + q]);
        unsigned a1 = __float_as_uint(arow1[kk * 8 + q]);
        unsigned a2 = __float_as_uint(arow0[kk * 8 + q + 4]);
        unsigned a3 = __float_as_uint(arow1[kk * 8 + q + 4]);
#pragma unroll
        for (int n = 0; n < 12; n++) {
            float2 b = __ldg(&wf[(kk * 12 + n) * 32]);
            asm volatile(
                "mma.sync.aligned.m16n8k8.row.col.f32.tf32.tf32.f32 "
                "{%0,%1,%2,%3}, {%4,%5,%6,%7}, {%8,%9}, {%0,%1,%2,%3};"
                : "+f"(d[n * 4]), "+f"(d[n * 4 + 1]), "+f"(d[n * 4 + 2]), "+f"(d[n * 4 + 3])
                : "r"(a0), "r"(a1), "r"(a2), "r"(a3),
                  "r"(__float_as_uint(b.x)), "r"(__float_as_uint(b.y)));
        }
    }
    __syncthreads();                                  // all hs reads done

    {   // dump D fragments into hs (reused as output tile)
        float* tb = hs + (warp * 16 + g) * 98;
#pragma unroll
        for (int n = 0; n < 12; n++) {
            int col = n * 8 + 2 * q;
            *(float2*)(tb + col)          = make_float2(d[n * 4],     d[n * 4 + 1]);
            *(float2*)(tb + 8 * 98 + col) = make_float2(d[n * 4 + 2], d[n * 4 + 3]);
        }
    }
    __syncthreads();

    for (int f = tid; f < 64 * D; f += 128) {
        int r = f / D, c = f - r * D;
        if (r < nvalid) {
            float v = hs[r * 98 + c] + __ldg(bias + c);
            if (stage == 0) v = fmaxf(v, 0.f);
            hout[(ll)(node0 + r) * D + c] = v;
        }
    }
    if (stage == 1 && tid < D) {
        float bc = __ldg(bias + tid);
        float s1 = 0.f, s2 = 0.f;
        for (int r = 0; r < nvalid; r++) {
            float v = hs[r * 98 + tid] + bc;
            s1 += v; s2 += v * v;
        }
        atomicAdd(&g_sum[tid],   s1);
        atomicAdd(&g_sumsq[tid], s2);
    }
}

// ---------------- batchnorm + relu ----------------
__global__ void k_bn(const float* __restrict__ gamma,
                     const float* __restrict__ beta,
                     float* __restrict__ out)
{
    int i = blockIdx.x * blockDim.x + threadIdx.x;
    const int TOT4 = NN * D / 4;
    if (i >= TOT4) return;
    int c = (i * 4) % D;
    const float invN = 1.0f / (float)NN;
    float4 h = ((const float4*)g_h2)[i];
    float hv[4] = {h.x, h.y, h.z, h.w};
    float o[4];
#pragma unroll
    for (int u = 0; u < 4; u++) {
        int cc = c + u;
        float mean = g_sum[cc] * invN;
        float var  = g_sumsq[cc] * invN - mean * mean;
        float inv  = rsqrtf(var + 1e-5f);
        o[u] = fmaxf((hv[u] - mean) * inv * gamma[cc] + beta[cc], 0.f);
    }
    ((float4*)out)[i] = make_float4(o[0], o[1], o[2], o[3]);
}

// ---------------- launch (edgemsg at profiled slot 3) ----------------
extern "C" void kernel_launch(void* const* d_in, const int* in_sizes, int n_in,
                              void* d_out, int out_size)
{
    const float* x     = (const float*)d_in[0];
    const void*  ei    = d_in[1];
    const float* ea    = (const float*)d_in[2];
    const float* We    = (const float*)d_in[3];
    const float* be    = (const float*)d_in[4];
    const float* W1    = (const float*)d_in[5];
    const float* b1    = (const float*)d_in[6];
    const float* W2    = (const float*)d_in[7];
    const float* b2    = (const float*)d_in[8];
    const float* gamma = (const float*)d_in[9];
    const float* beta  = (const float*)d_in[10];
    float*       out   = (float*)d_out;

    k_init   <<<(NN + 255) / 256, 256>>>((const unsigned int*)ei);   // 0
    k_count  <<<(EE + 255) / 256, 256>>>(ei);                        // 1
    k_scan1  <<<NB, 128>>>();                                        // 2
    k_edgemsg<<<EE / 128, 256>>>(ea, We, be);                        // 3  <- profiled slot
    k_scan2  <<<1, 512>>>();                                         // 4
    k_scan3  <<<NB, 128>>>();                                        // 5
    k_fill   <<<(EE + 255) / 256, 256>>>(ei);                        // 6
    k_prep   <<<(2 * 4608 + 255) / 256, 256>>>(W1, W2);              // 7
    k_aggr   <<<NN / 8, 256>>>(x);                                   // 8
    k_mlp    <<<(NN + 63) / 64, 128>>>(b1, 0);                       // 9
    k_mlp    <<<(NN + 63) / 64, 128>>>(b2, 1);                       // 10
    k_bn     <<<(NN * D / 4 + 255) / 256, 256>>>(gamma, beta, out);  // 11
}